// round 6
// baseline (speedup 1.0000x reference)
#include <cuda_runtime.h>

#define D 128
#define KK 256            // 2*D concatenated input width
#define TILE_ROWS 64
#define IN_STRIDE 260     // 256 + 4 pad (floats)
#define W_STRIDE 132      // 128 + 4 pad (floats)
#define SLOT_CAP 96
#define MAXN 65536
#define LN_EPS 1e-5f

// Scratch (no allocations allowed): format flag + degree counters + per-node source lists.
__device__ int g_fmt64;                       // 1 if edge_index is int64, 0 if int32
__device__ int g_deg[MAXN];
__device__ int g_slots[(size_t)MAXN * SLOT_CAP];

// Probe: decide whether the edge buffer is int64 or int32.
// int64 values < 2^31 look like (lo, 0, lo, 0, ...) when read as int32:
// count zeros at odd int32 positions in the first 2048 words.
__global__ void probe_fmt_kernel(const int* __restrict__ ei32) {
    __shared__ int zc;
    if (threadIdx.x == 0) zc = 0;
    __syncthreads();
    int i = threadIdx.x;                      // 256 threads, 4 odd-slots each
    int local = 0;
    #pragma unroll
    for (int j = 0; j < 4; j++) {
        int pos = 2 * (i + 256 * j) + 1;      // odd positions 1,3,...,2047
        if (ei32[pos] == 0) local++;
    }
    atomicAdd(&zc, local);
    __syncthreads();
    if (threadIdx.x == 0) g_fmt64 = (zc > 512) ? 1 : 0;
}

__global__ void zero_deg_kernel(int n) {
    int i = blockIdx.x * blockDim.x + threadIdx.x;
    if (i < n) g_deg[i] = 0;
}

// One thread per edge: histogram destination degree and record source id.
// Range-checked so that no dtype misinterpretation can ever produce a wild atomic.
__global__ void build_slots_kernel(const void* __restrict__ ei_raw, int E, int N) {
    int e = blockIdx.x * blockDim.x + threadIdx.x;
    if (e >= E) return;
    int s, d;
    if (g_fmt64) {
        const long long* ei = (const long long*)ei_raw;
        s = (int)ei[e];
        d = (int)ei[(size_t)E + e];
    } else {
        const int* ei = (const int*)ei_raw;
        s = ei[e];
        d = ei[E + e];
    }
    if ((unsigned)d >= (unsigned)N || (unsigned)s >= (unsigned)N) return;
    int p = atomicAdd(&g_deg[d], 1);
    if (p < SLOT_CAP) g_slots[d * SLOT_CAP + p] = s;
}

// Persistent fused kernel: gather-mean -> [mean|x] @ [Wl;Wr]^T + b -> LN -> ReLU
__global__ __launch_bounds__(256, 1) void fused_gnn_kernel(
    const float* __restrict__ x,
    const float* __restrict__ Wl, const float* __restrict__ bl,
    const float* __restrict__ Wr,
    const float* __restrict__ gamma, const float* __restrict__ beta,
    float* __restrict__ out, int N)
{
    extern __shared__ float smem[];
    float* Wt = smem;                          // [KK][W_STRIDE]  (transposed weights)
    float* In = smem + KK * W_STRIDE;          // [TILE_ROWS][IN_STRIDE]

    const int tid = threadIdx.x;
    const int tx  = tid & 31;    // column quad: cols 4*tx .. 4*tx+3
    const int wrp = tid >> 5;    // warp id: rows wrp*8 .. wrp*8+7

    // Load W transposed into SMEM once (persistent CTA): Wt[k][c]
    for (int idx = tid; idx < D * D; idx += 256) {
        int c = idx >> 7, k = idx & 127;
        Wt[k * W_STRIDE + c]       = Wl[idx];   // Wl is [c][k] row-major
        Wt[(k + D) * W_STRIDE + c] = Wr[idx];
    }
    const float4 ga = *(const float4*)(gamma + 4 * tx);
    const float4 be = *(const float4*)(beta  + 4 * tx);
    const float4 bb = *(const float4*)(bl    + 4 * tx);
    __syncthreads();

    const int k4 = (tid & 63) * 4;   // staging column chunk (0..252)
    const int rb = tid >> 6;         // staging row base (0..3)

    for (int tile = blockIdx.x * TILE_ROWS; tile < N; tile += gridDim.x * TILE_ROWS) {
        // ---- Stage In[r][k]: k<128 -> mean over gathered neighbors, k>=128 -> x ----
        for (int r = rb; r < TILE_ROWS; r += 4) {
            int g = tile + r;
            float4 v = make_float4(0.f, 0.f, 0.f, 0.f);
            if (g < N) {
                if (k4 < D) {
                    int dg = g_deg[g];
                    int m  = dg < SLOT_CAP ? dg : SLOT_CAP;
                    const int* sl = g_slots + g * SLOT_CAP;
                    float s0 = 0.f, s1 = 0.f, s2 = 0.f, s3 = 0.f;
                    for (int j = 0; j < m; j++) {
                        float4 xv = *(const float4*)(x + sl[j] * D + k4);
                        s0 += xv.x; s1 += xv.y; s2 += xv.z; s3 += xv.w;
                    }
                    float ic = 1.0f / fmaxf((float)dg, 1.0f);
                    v = make_float4(s0 * ic, s1 * ic, s2 * ic, s3 * ic);
                } else {
                    v = *(const float4*)(x + g * D + (k4 - D));
                }
            }
            *(float4*)(In + r * IN_STRIDE + k4) = v;
        }
        __syncthreads();

        // ---- GEMM micro-tile: 8 rows x 4 cols per thread ----
        float acc[8][4];
        #pragma unroll
        for (int r = 0; r < 8; r++) {
            acc[r][0] = 0.f; acc[r][1] = 0.f; acc[r][2] = 0.f; acc[r][3] = 0.f;
        }
        const float* inb = In + (wrp * 8) * IN_STRIDE;

        #pragma unroll 4
        for (int k = 0; k < KK; k += 4) {
            float4 w0 = *(const float4*)(Wt + (k + 0) * W_STRIDE + 4 * tx);
            float4 w1 = *(const float4*)(Wt + (k + 1) * W_STRIDE + 4 * tx);
            float4 w2 = *(const float4*)(Wt + (k + 2) * W_STRIDE + 4 * tx);
            float4 w3 = *(const float4*)(Wt + (k + 3) * W_STRIDE + 4 * tx);
            #pragma unroll
            for (int r = 0; r < 8; r++) {
                float4 a = *(const float4*)(inb + r * IN_STRIDE + k);
                acc[r][0] = fmaf(a.x, w0.x, fmaf(a.y, w1.x, fmaf(a.z, w2.x, fmaf(a.w, w3.x, acc[r][0]))));
                acc[r][1] = fmaf(a.x, w0.y, fmaf(a.y, w1.y, fmaf(a.z, w2.y, fmaf(a.w, w3.y, acc[r][1]))));
                acc[r][2] = fmaf(a.x, w0.z, fmaf(a.y, w1.z, fmaf(a.z, w2.z, fmaf(a.w, w3.z, acc[r][2]))));
                acc[r][3] = fmaf(a.x, w0.w, fmaf(a.y, w1.w, fmaf(a.z, w2.w, fmaf(a.w, w3.w, acc[r][3]))));
            }
        }

        // ---- Epilogue: +bias, LayerNorm (row fully inside one warp), ReLU ----
        #pragma unroll
        for (int r = 0; r < 8; r++) {
            int g = tile + wrp * 8 + r;
            float h0 = acc[r][0] + bb.x;
            float h1 = acc[r][1] + bb.y;
            float h2 = acc[r][2] + bb.z;
            float h3 = acc[r][3] + bb.w;
            float s1 = h0 + h1 + h2 + h3;
            float s2 = h0 * h0 + h1 * h1 + h2 * h2 + h3 * h3;
            #pragma unroll
            for (int off = 16; off > 0; off >>= 1) {
                s1 += __shfl_xor_sync(0xffffffffu, s1, off);
                s2 += __shfl_xor_sync(0xffffffffu, s2, off);
            }
            float mu  = s1 * (1.0f / D);
            float var = s2 * (1.0f / D) - mu * mu;
            float inv = rsqrtf(var + LN_EPS);
            if (g < N) {
                float4 o;
                o.x = fmaxf((h0 - mu) * inv * ga.x + be.x, 0.f);
                o.y = fmaxf((h1 - mu) * inv * ga.y + be.y, 0.f);
                o.z = fmaxf((h2 - mu) * inv * ga.z + be.z, 0.f);
                o.w = fmaxf((h3 - mu) * inv * ga.w + be.w, 0.f);
                *(float4*)(out + g * D + 4 * tx) = o;
            }
        }
        __syncthreads();   // protect In before next tile's staging
    }
}

extern "C" void kernel_launch(void* const* d_in, const int* in_sizes, int n_in,
                              void* d_out, int out_size) {
    const float* x     = (const float*)d_in[0];
    const void*  ei    = d_in[1];                 // int32 or int64 — probed at runtime
    const float* Wl    = (const float*)d_in[2];
    const float* bl    = (const float*)d_in[3];
    const float* Wr    = (const float*)d_in[4];
    const float* gamma = (const float*)d_in[5];
    const float* beta  = (const float*)d_in[6];
    float*       out   = (float*)d_out;

    int N = in_sizes[0] / D;
    int E = in_sizes[1] / 2;

    probe_fmt_kernel<<<1, 256>>>((const int*)ei);
    zero_deg_kernel<<<(N + 255) / 256, 256>>>(N);
    build_slots_kernel<<<(E + 255) / 256, 256>>>(ei, E, N);

    const size_t smem_bytes = (size_t)(KK * W_STRIDE + TILE_ROWS * IN_STRIDE) * sizeof(float);
    cudaFuncSetAttribute(fused_gnn_kernel,
                         cudaFuncAttributeMaxDynamicSharedMemorySize, (int)smem_bytes);
    fused_gnn_kernel<<<148, 256, smem_bytes>>>(x, Wl, bl, Wr, gamma, beta, out, N);
}

// round 7
// speedup vs baseline: 1.3278x; 1.3278x over previous
#include <cuda_runtime.h>

#define D 128
#define KK 256            // 2*D concatenated input width
#define TILE_ROWS 40      // rows per tile; 8 compute warps x 5 rows
#define ROWS_PER_WARP 5
#define SLOT_CAP 96
#define MAXN 65536
#define LN_EPS 1e-5f
#define NBLK 148
#define NTHREADS 512

// Scratch: format flag + degree counters + per-node source lists.
__device__ int g_fmt64;
__device__ int g_deg[MAXN];
__device__ int g_slots[(size_t)MAXN * SLOT_CAP];

// ---------------- build kernels (unchanged, proven) ----------------
__global__ void probe_fmt_kernel(const int* __restrict__ ei32) {
    __shared__ int zc;
    if (threadIdx.x == 0) zc = 0;
    __syncthreads();
    int local = 0;
    #pragma unroll
    for (int j = 0; j < 4; j++) {
        int pos = 2 * (threadIdx.x + 256 * j) + 1;
        if (ei32[pos] == 0) local++;
    }
    atomicAdd(&zc, local);
    __syncthreads();
    if (threadIdx.x == 0) g_fmt64 = (zc > 512) ? 1 : 0;
}

__global__ void zero_deg_kernel(int n) {
    int i = blockIdx.x * blockDim.x + threadIdx.x;
    if (i < n) g_deg[i] = 0;
}

__global__ void build_slots_kernel(const void* __restrict__ ei_raw, int E, int N) {
    int e = blockIdx.x * blockDim.x + threadIdx.x;
    if (e >= E) return;
    int s, d;
    if (g_fmt64) {
        const long long* ei = (const long long*)ei_raw;
        s = (int)ei[e];
        d = (int)ei[(size_t)E + e];
    } else {
        const int* ei = (const int*)ei_raw;
        s = ei[e];
        d = ei[E + e];
    }
    if ((unsigned)d >= (unsigned)N || (unsigned)s >= (unsigned)N) return;
    int p = atomicAdd(&g_deg[d], 1);
    if (p < SLOT_CAP) g_slots[d * SLOT_CAP + p] = s;
}

// ---------------- fused kernel ----------------
__device__ __forceinline__ void ffma2(unsigned long long& acc,
                                      unsigned long long a,
                                      unsigned long long b) {
    asm("fma.rn.f32x2 %0, %1, %2, %0;" : "+l"(acc) : "l"(a), "l"(b));
}
__device__ __forceinline__ float f2sum(unsigned long long v) {
    float2 f = *reinterpret_cast<float2*>(&v);
    return f.x + f.y;
}

// Warp-specialized persistent kernel:
//   warps 0-7:  GEMM (f32x2 packed) + bias + LayerNorm + ReLU on buffer `buf`
//   warps 8-15: stage next tile's [mean(neigh) | x] into buffer `buf^1`
__global__ __launch_bounds__(NTHREADS, 1) void fused_gnn_kernel(
    const float* __restrict__ x,
    const float* __restrict__ Wl, const float* __restrict__ bl,
    const float* __restrict__ Wr,
    const float* __restrict__ gamma, const float* __restrict__ beta,
    float* __restrict__ out, int N)
{
    extern __shared__ float smem[];
    // W, k-interleaved by 4: Wt[(k>>2)*512 + c*4 + (k&3)]  (KK/4=64 chunk-rows of 128 float4)
    float* Wt  = smem;                                // 32768 floats = 128KB
    float* In0 = smem + KK * D;                       // [TILE_ROWS][256]
    float* In1 = In0 + TILE_ROWS * KK;

    const int tid  = threadIdx.x;
    const int wid  = tid >> 5;
    const int lane = tid & 31;

    // ---- Load W interleaved (all 512 threads) ----
    for (int idx = tid; idx < D * D; idx += NTHREADS) {
        int c = idx >> 7, k = idx & 127;
        Wt[(k >> 2) * 512 + c * 4 + (k & 3)]        = Wl[idx];
        Wt[((k >> 2) + 32) * 512 + c * 4 + (k & 3)] = Wr[idx];
    }

    // Compute-warp constants (cols lane, lane+32, lane+64, lane+96)
    float bb[4], ga[4], be[4];
    if (wid < 8) {
        #pragma unroll
        for (int c = 0; c < 4; c++) {
            bb[c] = bl[lane + 32 * c];
            ga[c] = gamma[lane + 32 * c];
            be[c] = beta[lane + 32 * c];
        }
    }

    // Producer thread mapping
    const int pt    = tid - 256;           // 0..255 for producers
    const int k4    = (pt & 63) * 4;       // column chunk 0..252
    const int rbase = pt >> 6;             // 0..3

    const int stride = NBLK * TILE_ROWS;
    int t = blockIdx.x * TILE_ROWS;

    // Prologue: producers stage buffer 0 for the first tile
    if (wid >= 8 && t < N) {
        for (int r = rbase; r < TILE_ROWS; r += 4) {
            int g = t + r;
            float4 v = make_float4(0.f, 0.f, 0.f, 0.f);
            if (g < N) {
                if (k4 < D) {
                    int dg = g_deg[g];
                    int m  = dg < SLOT_CAP ? dg : SLOT_CAP;
                    const int* sl = g_slots + g * SLOT_CAP;
                    float s0 = 0.f, s1 = 0.f, s2 = 0.f, s3 = 0.f;
                    for (int j = 0; j < m; j++) {
                        float4 xv = *(const float4*)(x + sl[j] * D + k4);
                        s0 += xv.x; s1 += xv.y; s2 += xv.z; s3 += xv.w;
                    }
                    float ic = 1.0f / fmaxf((float)dg, 1.0f);
                    v = make_float4(s0 * ic, s1 * ic, s2 * ic, s3 * ic);
                } else {
                    v = *(const float4*)(x + g * D + (k4 - D));
                }
            }
            *(float4*)(In0 + r * KK + k4) = v;
        }
    }

    int buf = 0;
    for (; t < N; t += stride, buf ^= 1) {
        __syncthreads();   // buf ready for compute; buf^1 free for producers

        if (wid < 8) {
            // ================= GEMM (f32x2) =================
            const float* In = buf ? In1 : In0;
            const int row0 = wid * ROWS_PER_WARP;
            unsigned long long acc[ROWS_PER_WARP][4][2];
            #pragma unroll
            for (int r = 0; r < ROWS_PER_WARP; r++)
                #pragma unroll
                for (int c = 0; c < 4; c++) { acc[r][c][0] = 0ull; acc[r][c][1] = 0ull; }

            const ulonglong2* Wd = (const ulonglong2*)Wt;     // [64][128] 16B elems
            #pragma unroll 2
            for (int ch = 0; ch < 64; ch++) {
                ulonglong2 w0 = Wd[ch * 128 + lane];
                ulonglong2 w1 = Wd[ch * 128 + lane + 32];
                ulonglong2 w2 = Wd[ch * 128 + lane + 64];
                ulonglong2 w3 = Wd[ch * 128 + lane + 96];
                #pragma unroll
                for (int r = 0; r < ROWS_PER_WARP; r++) {
                    ulonglong2 a = ((const ulonglong2*)(In + (row0 + r) * KK))[ch];
                    ffma2(acc[r][0][0], a.x, w0.x); ffma2(acc[r][0][1], a.y, w0.y);
                    ffma2(acc[r][1][0], a.x, w1.x); ffma2(acc[r][1][1], a.y, w1.y);
                    ffma2(acc[r][2][0], a.x, w2.x); ffma2(acc[r][2][1], a.y, w2.y);
                    ffma2(acc[r][3][0], a.x, w3.x); ffma2(acc[r][3][1], a.y, w3.y);
                }
            }

            // ============ bias + LayerNorm + ReLU ============
            #pragma unroll
            for (int r = 0; r < ROWS_PER_WARP; r++) {
                int g = t + row0 + r;
                float h[4];
                #pragma unroll
                for (int c = 0; c < 4; c++)
                    h[c] = f2sum(acc[r][c][0]) + f2sum(acc[r][c][1]) + bb[c];
                float s1 = h[0] + h[1] + h[2] + h[3];
                float s2 = h[0]*h[0] + h[1]*h[1] + h[2]*h[2] + h[3]*h[3];
                #pragma unroll
                for (int off = 16; off > 0; off >>= 1) {
                    s1 += __shfl_xor_sync(0xffffffffu, s1, off);
                    s2 += __shfl_xor_sync(0xffffffffu, s2, off);
                }
                float mu  = s1 * (1.0f / D);
                float var = s2 * (1.0f / D) - mu * mu;
                float inv = rsqrtf(var + LN_EPS);
                if (g < N) {
                    #pragma unroll
                    for (int c = 0; c < 4; c++)
                        out[g * D + lane + 32 * c] =
                            fmaxf((h[c] - mu) * inv * ga[c] + be[c], 0.f);
                }
            }
        } else {
            // ================= stage next tile into buf^1 =================
            int tn = t + stride;
            if (tn < N) {
                float* In = buf ? In0 : In1;
                for (int r = rbase; r < TILE_ROWS; r += 4) {
                    int g = tn + r;
                    float4 v = make_float4(0.f, 0.f, 0.f, 0.f);
                    if (g < N) {
                        if (k4 < D) {
                            int dg = g_deg[g];
                            int m  = dg < SLOT_CAP ? dg : SLOT_CAP;
                            const int* sl = g_slots + g * SLOT_CAP;
                            float s0 = 0.f, s1 = 0.f, s2 = 0.f, s3 = 0.f;
                            for (int j = 0; j < m; j++) {
                                float4 xv = *(const float4*)(x + sl[j] * D + k4);
                                s0 += xv.x; s1 += xv.y; s2 += xv.z; s3 += xv.w;
                            }
                            float ic = 1.0f / fmaxf((float)dg, 1.0f);
                            v = make_float4(s0 * ic, s1 * ic, s2 * ic, s3 * ic);
                        } else {
                            v = *(const float4*)(x + g * D + (k4 - D));
                        }
                    }
                    *(float4*)(In + r * KK + k4) = v;
                }
            }
        }
    }
}

extern "C" void kernel_launch(void* const* d_in, const int* in_sizes, int n_in,
                              void* d_out, int out_size) {
    const float* x     = (const float*)d_in[0];
    const void*  ei    = d_in[1];
    const float* Wl    = (const float*)d_in[2];
    const float* bl    = (const float*)d_in[3];
    const float* Wr    = (const float*)d_in[4];
    const float* gamma = (const float*)d_in[5];
    const float* beta  = (const float*)d_in[6];
    float*       out   = (float*)d_out;

    int N = in_sizes[0] / D;
    int E = in_sizes[1] / 2;

    probe_fmt_kernel<<<1, 256>>>((const int*)ei);
    zero_deg_kernel<<<(N + 255) / 256, 256>>>(N);
    build_slots_kernel<<<(E + 255) / 256, 256>>>(ei, E, N);

    const size_t smem_bytes = (size_t)(KK * D + 2 * TILE_ROWS * KK) * sizeof(float); // 208KB
    cudaFuncSetAttribute(fused_gnn_kernel,
                         cudaFuncAttributeMaxDynamicSharedMemorySize, (int)smem_bytes);
    fused_gnn_kernel<<<NBLK, NTHREADS, smem_bytes>>>(x, Wl, bl, Wr, gamma, beta, out, N);
}